// round 7
// baseline (speedup 1.0000x reference)
#include <cuda_runtime.h>

#define NSTATE 65536
#define BMAX   1024

__device__ __align__(16) float g_state[(size_t)BMAX * NSTATE];

__device__ __forceinline__ unsigned long long pk2(float a, float b) {
  unsigned long long r;
  asm("mov.b64 %0, {%1, %2};" : "=l"(r) : "f"(a), "f"(b));
  return r;
}

// tan-form RY (packed): lo' = lo - t*hi ; hi' = hi + t*lo   (cos factored out)
template<int S2>
__device__ __forceinline__ void ry2t(float2* r, float t) {
  const unsigned long long t2 = pk2(t, t), nt2 = pk2(-t, -t);
#pragma unroll
  for (int base = 0; base < 32; base += 2 * S2)
#pragma unroll
    for (int k = 0; k < S2; k++) {
      unsigned long long lo = *(unsigned long long*)&r[base + k];
      unsigned long long hi = *(unsigned long long*)&r[base + k + S2];
      unsigned long long nlo, nhi;
      asm("fma.rn.f32x2 %0, %1, %2, %3;" : "=l"(nlo) : "l"(nt2), "l"(hi), "l"(lo));
      asm("fma.rn.f32x2 %0, %1, %2, %3;" : "=l"(nhi) : "l"(t2),  "l"(lo), "l"(hi));
      *(unsigned long long*)&r[base + k]      = nlo;
      *(unsigned long long*)&r[base + k + S2] = nhi;
    }
}

// tan-form RY inside each float2
__device__ __forceinline__ void ryct(float2* r, float t) {
#pragma unroll
  for (int i = 0; i < 32; i++) {
    float x = r[i].x, y = r[i].y;
    r[i].x = fmaf(-t, y, x);
    r[i].y = fmaf( t, x, y);
  }
}

__device__ __forceinline__ void scale32(float2* r, float c) {
  const unsigned long long c2 = pk2(c, c);
#pragma unroll
  for (int i = 0; i < 32; i++) {
    unsigned long long v = *(unsigned long long*)&r[i], o;
    asm("mul.rn.f32x2 %0, %1, %2;" : "=l"(o) : "l"(c2), "l"(v));
    *(unsigned long long*)&r[i] = o;
  }
}

template<int C2, int T2>
__device__ __forceinline__ void cnot2(float2* r) {
#pragma unroll
  for (int i = 0; i < 32; i++)
    if ((i & C2) && !(i & T2)) { float2 t = r[i]; r[i] = r[i | T2]; r[i | T2] = t; }
}
template<int C2>
__device__ __forceinline__ void cnotc(float2* r) {
#pragma unroll
  for (int i = 0; i < 32; i++)
    if (i & C2) { float t = r[i].x; r[i].x = r[i].y; r[i].y = t; }
}

#define TILE_F   2176                 // 32 rows * 68 floats (pad 4/row)
#define TILES_F  (8 * TILE_F)
// tiles + wc128 + ws128 + wt128 + CS16 + eA0 16 + eA1 16 + chi64 + psi64 + PM16 + rbuf16
#define SMEM_FLOATS (TILES_F + 128 + 128 + 128 + 16 + 16 + 16 + 64 + 64 + 16 + 16)
#define SMEM_BYTES  (SMEM_FLOATS * 4)

__global__ void __launch_bounds__(256, 3)
vqc_kernel(const float* __restrict__ x, const float* __restrict__ w,
           float* __restrict__ out)
{
  extern __shared__ float sm[];
  float* tiles = sm;
  float* wc  = sm + TILES_F;      // [8][16] cos(w/2)
  float* ws  = wc + 128;          // [8][16] sin(w/2)
  float* wt  = ws + 128;          // [8][16] tan(w/2)
  float* CS  = wt + 128;          // [8] per-layer cos-product scale
  float* eA0 = CS + 16;           // [16]
  float* eA1 = eA0 + 16;          // [16]
  float* chi = eA1 + 16;          // [64] q0..5 factor after layer-0 pass-1 gates
  float* psi = chi + 64;          // [64] q10..15 factor after layer-0 L gates
  float* PM  = psi + 64;          // [16] q6..9 product
  float* rbuf = PM + 16;          // [16]

  const int b = blockIdx.x, tid = threadIdx.x;
  const int lane = tid & 31, wid = tid >> 5;
  float* st     = g_state + (size_t)b * NSTATE;
  float* mytile = tiles + wid * TILE_F;

  if (tid < 128) {
    float c, s; sincosf(0.5f * w[tid], &s, &c);
    wc[tid] = c; ws[tid] = s; wt[tid] = s / c;
  } else if (tid < 144) {
    int q = tid - 128;
    float c, s; sincosf(0.5f * x[b * 16 + q], &s, &c);
    eA0[q] = (c - s) * 0.7071067811865476f;
    eA1[q] = (c + s) * 0.7071067811865476f;
  }
  if (tid < 16) rbuf[tid] = 0.f;
  __syncthreads();

  // per-layer cos-product: d=0 -> q5..10 (only M gates run tan-form);
  // d=7 -> q0..10 (L group dropped); else full q0..15
  if (tid < 8) {
    int d = tid; float p = 1.f;
    int qa = (d == 0) ? 5 : 0;
    int qb = (d == 7 || d == 0) ? 10 : 15;
    for (int q = qa; q <= qb; q++) p *= wc[d * 16 + q];
    CS[d] = p;
  }

  // product factors: chi bit5=q0..bit0=q5 ; psi bit5=q10..bit0=q15 ; PM bit3=q6..bit0=q9
  if (tid < 64) {
    float p = 1.f, p2 = 1.f;
#pragma unroll
    for (int k = 0; k < 6; k++) {
      int bit = (tid >> (5 - k)) & 1;
      p  *= bit ? eA1[k]      : eA0[k];
      p2 *= bit ? eA1[10 + k] : eA0[10 + k];
    }
    chi[tid] = p; psi[tid] = p2;
  }
  if (tid < 16) {
    float p = ((tid & 8) ? eA1[6] : eA0[6]) * ((tid & 4) ? eA1[7] : eA0[7])
            * ((tid & 2) ? eA1[8] : eA0[8]) * ((tid & 1) ? eA1[9] : eA0[9]);
    PM[tid] = p;
  }
  __syncthreads();

  // layer-0 exact gates on chi (E(0,1)(2,3)(4,5); O(1,2)(3,4); RY(0..4))
  // and psi (E(10,11)(12,13)(14,15); O(11,12)(13,14); RY(11..15))
  {
    float vc = 0.f, vp = 0.f;
    if (tid < 64) {
      int g = tid;
      if (g & 16) g ^= 8;  if (g & 4)  g ^= 2;
      if (g & 32) g ^= 16; if (g & 8)  g ^= 4; if (g & 2) g ^= 1;
      vc = chi[g]; vp = psi[g];
    }
    __syncthreads();
    if (tid < 64) { chi[tid] = vc; psi[tid] = vp; }
    __syncthreads();
#pragma unroll 1
    for (int k = 0; k < 5; k++) {
      const int mA = 32 >> k, mB = 16 >> k;
      const float cA = wc[k], sA = ws[k], cB = wc[11 + k], sB = ws[11 + k];
      float a1 = 0.f, b1 = 0.f, a2 = 0.f, b2 = 0.f;
      if (tid < 64) { a1 = chi[tid]; b1 = chi[tid ^ mA]; a2 = psi[tid]; b2 = psi[tid ^ mB]; }
      __syncthreads();
      if (tid < 64) {
        chi[tid] = (tid & mA) ? fmaf(cA, a1, sA * b1) : fmaf(cA, a1, -(sA * b1));
        psi[tid] = (tid & mB) ? fmaf(cB, a2, sB * b2) : fmaf(cB, a2, -(sB * b2));
      }
      __syncthreads();
    }
  }

  float acc[10];
#pragma unroll
  for (int q = 0; q < 10; q++) acc[q] = 0.f;

#pragma unroll 1
  for (int d = 0; d < 8; d++) {
    const float* lt = wt + d * 16;

    // ===== Pass 1: q0..5 (idx bits 15..10); coalesced stride-4KB scalar =====
    if (d > 0) {
#pragma unroll 1
      for (int it = 0; it < 4; it++) {
        float* base = st + it * 256 + tid;
        float2 r[32];              // fi: q0=16,q1=8,q2=4,q3=2,q4=1 ; comp=q5
#pragma unroll
        for (int j = 0; j < 32; j++) {
          r[j].x = base[(2 * j) * 1024];
          r[j].y = base[(2 * j + 1) * 1024];
        }
        cnot2<16, 8>(r); cnot2<4, 2>(r); cnotc<1>(r);   // E(0,1)(2,3)(4,5)
        cnot2<8, 4>(r);  cnot2<2, 1>(r);                // O(1,2)(3,4)
        ry2t<16>(r, lt[0]);
        ry2t<8> (r, lt[1]);
        ry2t<4> (r, lt[2]);
        ry2t<2> (r, lt[3]);
        ry2t<1> (r, lt[4]);                             // RY(5) deferred to M
#pragma unroll
        for (int j = 0; j < 32; j++) {
          base[(2 * j) * 1024]     = r[j].x;
          base[(2 * j + 1) * 1024] = r[j].y;
        }
      }
      __syncthreads();
    }

    // ===== Pass 2: per-warp 8KB supertile, idx bits 10..0 ; s = bits 15..11 =====
#pragma unroll 1
    for (int it = 0; it < 4; it++) {
      const int s = it * 8 + wid;
      float2 m2[32];               // fi: q5=16,q6=8,q7=4,q8=2,q9=1 ; comp=q10
      if (d == 0) {
        const float C0 = chi[2 * s], C1 = chi[2 * s + 1];
        const float p0 = psi[lane], p1 = psi[32 + lane];
#pragma unroll
        for (int fj = 0; fj < 32; fj++) {
          float bse = ((fj & 16) ? C1 : C0) * PM[fj & 15];
          m2[fj] = make_float2(bse * p0, bse * p1);
        }
      } else {
        const float4* g4 = (const float4*)(st + s * 2048);
#pragma unroll
        for (int i = 0; i < 16; i++) {
          float4 v = g4[i * 32 + lane];
          *(float4*)(mytile + 136 * i + 4 * lane + 4 * (lane >> 4)) = v;
        }
        __syncwarp();
        if (d < 7) {
          // L phase: row = lane; fi: q10=16,q11=8,q12=4,q13=2,q14=1 ; comp=q15
          float2 r[32];
#pragma unroll
          for (int k = 0; k < 16; k++) {
            float4 v = *(const float4*)(mytile + 68 * lane + 4 * k);
            r[2 * k]     = make_float2(v.x, v.y);
            r[2 * k + 1] = make_float2(v.z, v.w);
          }
          cnot2<16, 8>(r); cnot2<4, 2>(r); cnotc<1>(r); // E(10,11)(12,13)(14,15)
          cnot2<8, 4>(r);  cnot2<2, 1>(r);              // O(11,12)(13,14)
          ry2t<8>(r, lt[11]);
          ry2t<4>(r, lt[12]);
          ry2t<2>(r, lt[13]);
          ry2t<1>(r, lt[14]);
          ryct   (r, lt[15]);                           // RY(10) deferred to M
#pragma unroll
          for (int k = 0; k < 16; k++)
            *(float4*)(mytile + 68 * lane + 4 * k) =
              make_float4(r[2 * k].x, r[2 * k].y, r[2 * k + 1].x, r[2 * k + 1].y);
          __syncwarp();
#pragma unroll
          for (int fj = 0; fj < 32; fj++) {
            m2[fj].x = mytile[68 * fj + lane];
            m2[fj].y = mytile[68 * fj + 32 + lane];
          }
        } else {
          // layer 7: only CNOT(10,11) of the L group affects q0..9 -> fold into addressing
#pragma unroll
          for (int fj = 0; fj < 32; fj++) {
            m2[fj].x = mytile[68 * fj + lane];
            m2[fj].y = mytile[68 * fj + 32 + (lane ^ 16)];
          }
        }
      }
      // M gates (q5..10), tan-form
      cnot2<8, 4>(m2); cnot2<2, 1>(m2);                 // E(6,7)(8,9)
      cnot2<16, 8>(m2); cnot2<4, 2>(m2); cnotc<1>(m2);  // O(5,6)(7,8)(9,10)
      ry2t<16>(m2, lt[5]);
      ry2t<8> (m2, lt[6]);
      ry2t<4> (m2, lt[7]);
      ry2t<2> (m2, lt[8]);
      ry2t<1> (m2, lt[9]);
      ryct    (m2, lt[10]);
      if (d < 7) {
        scale32(m2, CS[d]);                             // fold all cos factors once
        float* o = st + s * 2048 + lane;
#pragma unroll
        for (int fj = 0; fj < 32; fj++) {
          o[(2 * fj) * 32]     = m2[fj].x;
          o[(2 * fj + 1) * 32] = m2[fj].y;
        }
      } else {
        float T = 0.f, m5 = 0.f, m6 = 0.f, m7 = 0.f, m8 = 0.f, m9 = 0.f;
#pragma unroll
        for (int i = 0; i < 32; i++) {
          float p = fmaf(m2[i].x, m2[i].x, m2[i].y * m2[i].y);
          T += p;
          if (i & 16) m5 += p;
          if (i & 8)  m6 += p;
          if (i & 4)  m7 += p;
          if (i & 2)  m8 += p;
          if (i & 1)  m9 += p;
        }
        const float sc2 = CS[7] * CS[7];                // scale probabilities once
        T *= sc2; m5 *= sc2; m6 *= sc2; m7 *= sc2; m8 *= sc2; m9 *= sc2;
#pragma unroll
        for (int q = 0; q < 5; q++)
          acc[q] += ((s >> (4 - q)) & 1) ? -T : T;
        acc[5] += T - 2.f * m5;
        acc[6] += T - 2.f * m6;
        acc[7] += T - 2.f * m7;
        acc[8] += T - 2.f * m8;
        acc[9] += T - 2.f * m9;
      }
    }
    __syncthreads();
  }

#pragma unroll
  for (int q = 0; q < 10; q++)
#pragma unroll
    for (int off = 16; off > 0; off >>= 1)
      acc[q] += __shfl_xor_sync(0xffffffffu, acc[q], off);
  if (lane == 0)
#pragma unroll
    for (int q = 0; q < 10; q++) atomicAdd(&rbuf[q], acc[q]);
  __syncthreads();
  if (tid < 10) out[b * 10 + tid] = rbuf[tid];
}

extern "C" void kernel_launch(void* const* d_in, const int* in_sizes, int n_in,
                              void* d_out, int out_size) {
  const float* x = (const float*)d_in[0];
  const float* w = (const float*)d_in[1];
  float* out = (float*)d_out;
  int B = in_sizes[0] / 16;
  if (B > BMAX) B = BMAX;
  cudaFuncSetAttribute(vqc_kernel, cudaFuncAttributeMaxDynamicSharedMemorySize,
                       SMEM_BYTES);
  vqc_kernel<<<B, 256, SMEM_BYTES>>>(x, w, out);
}

// round 8
// speedup vs baseline: 1.2480x; 1.2480x over previous
#include <cuda_runtime.h>

#define NSTATE 65536
#define BMAX   1024

__device__ __align__(16) float g_state[(size_t)BMAX * NSTATE];

__device__ __forceinline__ unsigned long long pk2(float a, float b) {
  unsigned long long r;
  asm("mov.b64 %0, {%1, %2};" : "=l"(r) : "f"(a), "f"(b));
  return r;
}

// tan-form RY (packed): lo' = lo - t*hi ; hi' = hi + t*lo   (cos factored out)
template<int S2>
__device__ __forceinline__ void ry2t(float2* r, float t) {
  const unsigned long long t2 = pk2(t, t), nt2 = pk2(-t, -t);
#pragma unroll
  for (int base = 0; base < 32; base += 2 * S2)
#pragma unroll
    for (int k = 0; k < S2; k++) {
      unsigned long long lo = *(unsigned long long*)&r[base + k];
      unsigned long long hi = *(unsigned long long*)&r[base + k + S2];
      unsigned long long nlo, nhi;
      asm("fma.rn.f32x2 %0, %1, %2, %3;" : "=l"(nlo) : "l"(nt2), "l"(hi), "l"(lo));
      asm("fma.rn.f32x2 %0, %1, %2, %3;" : "=l"(nhi) : "l"(t2),  "l"(lo), "l"(hi));
      *(unsigned long long*)&r[base + k]      = nlo;
      *(unsigned long long*)&r[base + k + S2] = nhi;
    }
}

// tan-form RY inside each float2
__device__ __forceinline__ void ryct(float2* r, float t) {
#pragma unroll
  for (int i = 0; i < 32; i++) {
    float x = r[i].x, y = r[i].y;
    r[i].x = fmaf(-t, y, x);
    r[i].y = fmaf( t, x, y);
  }
}

__device__ __forceinline__ void scale32(float2* r, float c) {
  const unsigned long long c2 = pk2(c, c);
#pragma unroll
  for (int i = 0; i < 32; i++) {
    unsigned long long v = *(unsigned long long*)&r[i], o;
    asm("mul.rn.f32x2 %0, %1, %2;" : "=l"(o) : "l"(c2), "l"(v));
    *(unsigned long long*)&r[i] = o;
  }
}

template<int C2, int T2>
__device__ __forceinline__ void cnot2(float2* r) {
#pragma unroll
  for (int i = 0; i < 32; i++)
    if ((i & C2) && !(i & T2)) { float2 t = r[i]; r[i] = r[i | T2]; r[i | T2] = t; }
}
template<int C2>
__device__ __forceinline__ void cnotc(float2* r) {
#pragma unroll
  for (int i = 0; i < 32; i++)
    if (i & C2) { float t = r[i].x; r[i].x = r[i].y; r[i].y = t; }
}

#define TILE_F   2176                 // 32 rows * 68 floats (pad 4/row)
#define TILES_F  (8 * TILE_F)
#define SMEM_FLOATS (TILES_F + 128 + 128 + 128 + 16 + 16 + 16 + 64 + 64 + 16 + 16)
#define SMEM_BYTES  (SMEM_FLOATS * 4)

__global__ void __launch_bounds__(256, 2)
vqc_kernel(const float* __restrict__ x, const float* __restrict__ w,
           float* __restrict__ out)
{
  extern __shared__ float sm[];
  float* tiles = sm;
  float* wc  = sm + TILES_F;      // [8][16] cos(w/2)
  float* ws  = wc + 128;          // [8][16] sin(w/2)
  float* wt  = ws + 128;          // [8][16] tan(w/2)
  float* CS  = wt + 128;          // [8] per-layer cos-product scale
  float* eA0 = CS + 16;           // [16]
  float* eA1 = eA0 + 16;          // [16]
  float* chi = eA1 + 16;          // [64] q0..5 factor after layer-0 pass-1 gates
  float* psi = chi + 64;          // [64] q10..15 factor after layer-0 L gates
  float* PM  = psi + 64;          // [16] q6..9 product
  float* rbuf = PM + 16;          // [16]

  const int b = blockIdx.x, tid = threadIdx.x;
  const int lane = tid & 31, wid = tid >> 5;
  float* st     = g_state + (size_t)b * NSTATE;
  float* mytile = tiles + wid * TILE_F;

  if (tid < 128) {
    float c, s; sincosf(0.5f * w[tid], &s, &c);
    wc[tid] = c; ws[tid] = s; wt[tid] = s / c;
  } else if (tid < 144) {
    int q = tid - 128;
    float c, s; sincosf(0.5f * x[b * 16 + q], &s, &c);
    eA0[q] = (c - s) * 0.7071067811865476f;
    eA1[q] = (c + s) * 0.7071067811865476f;
  }
  if (tid < 16) rbuf[tid] = 0.f;
  __syncthreads();

  // per-layer cos-product: d=0 -> q5..10 only; d=7 -> q0..10; else q0..15
  if (tid < 8) {
    int d = tid; float p = 1.f;
    int qa = (d == 0) ? 5 : 0;
    int qb = (d == 7 || d == 0) ? 10 : 15;
    for (int q = qa; q <= qb; q++) p *= wc[d * 16 + q];
    CS[d] = p;
  }

  // product factors: chi bit5=q0..bit0=q5 ; psi bit5=q10..bit0=q15 ; PM bit3=q6..bit0=q9
  if (tid < 64) {
    float p = 1.f, p2 = 1.f;
#pragma unroll
    for (int k = 0; k < 6; k++) {
      int bit = (tid >> (5 - k)) & 1;
      p  *= bit ? eA1[k]      : eA0[k];
      p2 *= bit ? eA1[10 + k] : eA0[10 + k];
    }
    chi[tid] = p; psi[tid] = p2;
  }
  if (tid < 16) {
    float p = ((tid & 8) ? eA1[6] : eA0[6]) * ((tid & 4) ? eA1[7] : eA0[7])
            * ((tid & 2) ? eA1[8] : eA0[8]) * ((tid & 1) ? eA1[9] : eA0[9]);
    PM[tid] = p;
  }
  __syncthreads();

  // layer-0 exact gates on chi (E(0,1)(2,3)(4,5); O(1,2)(3,4); RY(0..4))
  // and psi (E(10,11)(12,13)(14,15); O(11,12)(13,14); RY(11..15))
  {
    float vc = 0.f, vp = 0.f;
    if (tid < 64) {
      int g = tid;
      if (g & 16) g ^= 8;  if (g & 4)  g ^= 2;
      if (g & 32) g ^= 16; if (g & 8)  g ^= 4; if (g & 2) g ^= 1;
      vc = chi[g]; vp = psi[g];
    }
    __syncthreads();
    if (tid < 64) { chi[tid] = vc; psi[tid] = vp; }
    __syncthreads();
#pragma unroll 1
    for (int k = 0; k < 5; k++) {
      const int mA = 32 >> k, mB = 16 >> k;
      const float cA = wc[k], sA = ws[k], cB = wc[11 + k], sB = ws[11 + k];
      float a1 = 0.f, b1 = 0.f, a2 = 0.f, b2 = 0.f;
      if (tid < 64) { a1 = chi[tid]; b1 = chi[tid ^ mA]; a2 = psi[tid]; b2 = psi[tid ^ mB]; }
      __syncthreads();
      if (tid < 64) {
        chi[tid] = (tid & mA) ? fmaf(cA, a1, sA * b1) : fmaf(cA, a1, -(sA * b1));
        psi[tid] = (tid & mB) ? fmaf(cB, a2, sB * b2) : fmaf(cB, a2, -(sB * b2));
      }
      __syncthreads();
    }
  }

  float acc[10];
#pragma unroll
  for (int q = 0; q < 10; q++) acc[q] = 0.f;

#pragma unroll 1
  for (int d = 0; d < 8; d++) {
    const float* lt = wt + d * 16;

    // ===== Pass 1: q0..5 (idx bits 15..10); coalesced stride-4KB scalar =====
    if (d > 0) {
#pragma unroll 1
      for (int it = 0; it < 4; it++) {
        float* base = st + it * 256 + tid;
        float2 r[32];              // fi: q0=16,q1=8,q2=4,q3=2,q4=1 ; comp=q5
#pragma unroll
        for (int j = 0; j < 32; j++) {
          r[j].x = base[(2 * j) * 1024];
          r[j].y = base[(2 * j + 1) * 1024];
        }
        cnot2<16, 8>(r); cnot2<4, 2>(r); cnotc<1>(r);   // E(0,1)(2,3)(4,5)
        cnot2<8, 4>(r);  cnot2<2, 1>(r);                // O(1,2)(3,4)
        ry2t<16>(r, lt[0]);
        ry2t<8> (r, lt[1]);
        ry2t<4> (r, lt[2]);
        ry2t<2> (r, lt[3]);
        ry2t<1> (r, lt[4]);                             // RY(5) deferred to M
#pragma unroll
        for (int j = 0; j < 32; j++) {
          base[(2 * j) * 1024]     = r[j].x;
          base[(2 * j + 1) * 1024] = r[j].y;
        }
      }
      __syncthreads();
    }

    // ===== Pass 2: per-warp 8KB supertile, idx bits 10..0 ; s = bits 15..11 =====
#pragma unroll 1
    for (int it = 0; it < 4; it++) {
      const int s = it * 8 + wid;
      float2 m2[32];               // fi: q5=16,q6=8,q7=4,q8=2,q9=1 ; comp=q10
      if (d == 0) {
        const float C0 = chi[2 * s], C1 = chi[2 * s + 1];
        const float p0 = psi[lane], p1 = psi[32 + lane];
#pragma unroll
        for (int fj = 0; fj < 32; fj++) {
          float bse = ((fj & 16) ? C1 : C0) * PM[fj & 15];
          m2[fj] = make_float2(bse * p0, bse * p1);
        }
      } else {
        const float4* g4 = (const float4*)(st + s * 2048);
#pragma unroll
        for (int i = 0; i < 16; i++) {
          float4 v = g4[i * 32 + lane];
          *(float4*)(mytile + 136 * i + 4 * lane + 4 * (lane >> 4)) = v;
        }
        __syncwarp();
        if (d < 7) {
          // L phase: row = lane; fi: q10=16,q11=8,q12=4,q13=2,q14=1 ; comp=q15
          float2 r[32];
#pragma unroll
          for (int k = 0; k < 16; k++) {
            float4 v = *(const float4*)(mytile + 68 * lane + 4 * k);
            r[2 * k]     = make_float2(v.x, v.y);
            r[2 * k + 1] = make_float2(v.z, v.w);
          }
          cnot2<16, 8>(r); cnot2<4, 2>(r); cnotc<1>(r); // E(10,11)(12,13)(14,15)
          cnot2<8, 4>(r);  cnot2<2, 1>(r);              // O(11,12)(13,14)
          ry2t<8>(r, lt[11]);
          ry2t<4>(r, lt[12]);
          ry2t<2>(r, lt[13]);
          ry2t<1>(r, lt[14]);
          ryct   (r, lt[15]);                           // RY(10) deferred to M
#pragma unroll
          for (int k = 0; k < 16; k++)
            *(float4*)(mytile + 68 * lane + 4 * k) =
              make_float4(r[2 * k].x, r[2 * k].y, r[2 * k + 1].x, r[2 * k + 1].y);
          __syncwarp();
#pragma unroll
          for (int fj = 0; fj < 32; fj++) {
            m2[fj].x = mytile[68 * fj + lane];
            m2[fj].y = mytile[68 * fj + 32 + lane];
          }
        } else {
          // layer 7: only CNOT(10,11) of the L group affects q0..9 -> fold into addressing
#pragma unroll
          for (int fj = 0; fj < 32; fj++) {
            m2[fj].x = mytile[68 * fj + lane];
            m2[fj].y = mytile[68 * fj + 32 + (lane ^ 16)];
          }
        }
      }
      // M gates (q5..10), tan-form
      cnot2<8, 4>(m2); cnot2<2, 1>(m2);                 // E(6,7)(8,9)
      cnot2<16, 8>(m2); cnot2<4, 2>(m2); cnotc<1>(m2);  // O(5,6)(7,8)(9,10)
      ry2t<16>(m2, lt[5]);
      ry2t<8> (m2, lt[6]);
      ry2t<4> (m2, lt[7]);
      ry2t<2> (m2, lt[8]);
      ry2t<1> (m2, lt[9]);
      ryct    (m2, lt[10]);
      if (d < 7) {
        scale32(m2, CS[d]);                             // fold all cos factors once
        float* o = st + s * 2048 + lane;
#pragma unroll
        for (int fj = 0; fj < 32; fj++) {
          o[(2 * fj) * 32]     = m2[fj].x;
          o[(2 * fj + 1) * 32] = m2[fj].y;
        }
      } else {
        float T = 0.f, m5 = 0.f, m6 = 0.f, m7 = 0.f, m8 = 0.f, m9 = 0.f;
#pragma unroll
        for (int i = 0; i < 32; i++) {
          float p = fmaf(m2[i].x, m2[i].x, m2[i].y * m2[i].y);
          T += p;
          if (i & 16) m5 += p;
          if (i & 8)  m6 += p;
          if (i & 4)  m7 += p;
          if (i & 2)  m8 += p;
          if (i & 1)  m9 += p;
        }
        const float sc2 = CS[7] * CS[7];
        T *= sc2; m5 *= sc2; m6 *= sc2; m7 *= sc2; m8 *= sc2; m9 *= sc2;
#pragma unroll
        for (int q = 0; q < 5; q++)
          acc[q] += ((s >> (4 - q)) & 1) ? -T : T;
        acc[5] += T - 2.f * m5;
        acc[6] += T - 2.f * m6;
        acc[7] += T - 2.f * m7;
        acc[8] += T - 2.f * m8;
        acc[9] += T - 2.f * m9;
      }
    }
    __syncthreads();
  }

#pragma unroll
  for (int q = 0; q < 10; q++)
#pragma unroll
    for (int off = 16; off > 0; off >>= 1)
      acc[q] += __shfl_xor_sync(0xffffffffu, acc[q], off);
  if (lane == 0)
#pragma unroll
    for (int q = 0; q < 10; q++) atomicAdd(&rbuf[q], acc[q]);
  __syncthreads();
  if (tid < 10) out[b * 10 + tid] = rbuf[tid];
}

extern "C" void kernel_launch(void* const* d_in, const int* in_sizes, int n_in,
                              void* d_out, int out_size) {
  const float* x = (const float*)d_in[0];
  const float* w = (const float*)d_in[1];
  float* out = (float*)d_out;
  int B = in_sizes[0] / 16;
  if (B > BMAX) B = BMAX;
  cudaFuncSetAttribute(vqc_kernel, cudaFuncAttributeMaxDynamicSharedMemorySize,
                       SMEM_BYTES);
  vqc_kernel<<<B, 256, SMEM_BYTES>>>(x, w, out);
}